// round 8
// baseline (speedup 1.0000x reference)
#include <cuda_runtime.h>
#include <cuda_fp16.h>

#define Nn 100000
#define Ff 64
#define Ee 1600000
#define SCAN_B 98   // ceil(Nn/1024)

// Scratch (device globals — no allocation allowed anywhere)
__device__ float  g_deg[Nn];
__device__ float  g_dinv[Nn];
__device__ int    g_cnt[Nn];
__device__ int    g_off[Nn];
__device__ int    g_cursor[Nn];
__device__ int    g_bsum[128];
__device__ int    g_bbase[128];
__device__ int2   g_csr[Ee];          // (row, __float_as_int(nw))
__device__ float  g_h0[(size_t)Nn * Ff];
__device__ float  g_out1[(size_t)Nn * Ff];
__device__ __half g_h16[(size_t)Nn * Ff];   // fp16 shadow of h0   (gather src)
__device__ __half g_o16[(size_t)Nn * Ff];   // fp16 shadow of out1 (gather src)

// ---------------------------------------------------------------------------
__global__ void zero_kernel() {
    int i = blockIdx.x * blockDim.x + threadIdx.x;
    if (i < Nn) { g_deg[i] = 0.f; g_cnt[i] = 0; }
}

// ---------------------------------------------------------------------------
// deg[col[e]] += w[e];  cnt[col[e]] += 1
// ---------------------------------------------------------------------------
__global__ void deg_kernel(const int* __restrict__ cols,
                           const float* __restrict__ ew) {
    int e = blockIdx.x * blockDim.x + threadIdx.x;
    if (e < Ee) {
        unsigned c = (unsigned)cols[e];
        if (c < Nn) {
            atomicAdd(&g_deg[c], ew[e]);
            atomicAdd(&g_cnt[c], 1);
        }
    }
}

// ---------------------------------------------------------------------------
// 3-phase exclusive scan of g_cnt -> g_off/g_cursor (+ dinv fused in phase 3)
// ---------------------------------------------------------------------------
__global__ void __launch_bounds__(1024)
scan_sum_kernel() {
    __shared__ int sm[1024];
    int t = threadIdx.x;
    int i = blockIdx.x * 1024 + t;
    sm[t] = (i < Nn) ? g_cnt[i] : 0;
    __syncthreads();
    for (int d = 512; d > 0; d >>= 1) {
        if (t < d) sm[t] += sm[t + d];
        __syncthreads();
    }
    if (t == 0) g_bsum[blockIdx.x] = sm[0];
}

__global__ void __launch_bounds__(128)
scan_base_kernel() {
    __shared__ int sm[128];
    int t = threadIdx.x;
    int v = (t < SCAN_B) ? g_bsum[t] : 0;
    sm[t] = v;
    __syncthreads();
    for (int d = 1; d < 128; d <<= 1) {
        int u = (t >= d) ? sm[t - d] : 0;
        __syncthreads();
        sm[t] += u;
        __syncthreads();
    }
    if (t < SCAN_B) g_bbase[t] = sm[t] - v;  // exclusive
}

__global__ void __launch_bounds__(1024)
scan_final_kernel() {
    __shared__ int sm[1024];
    int t = threadIdx.x;
    int i = blockIdx.x * 1024 + t;
    int v = (i < Nn) ? g_cnt[i] : 0;
    sm[t] = v;
    __syncthreads();
    for (int d = 1; d < 1024; d <<= 1) {
        int u = (t >= d) ? sm[t - d] : 0;
        __syncthreads();
        sm[t] += u;
        __syncthreads();
    }
    if (i < Nn) {
        int off = g_bbase[blockIdx.x] + sm[t] - v;
        g_off[i] = off;
        g_cursor[i] = off;
        float d = g_deg[i];                      // dinv fused here
        g_dinv[i] = d > 0.f ? rsqrtf(d) : 0.f;
    }
}

// ---------------------------------------------------------------------------
// Scatter edges into packed CSR slots (one 8B write per edge).
// ---------------------------------------------------------------------------
__global__ void scatter_kernel(const int* __restrict__ rows,
                               const int* __restrict__ cols,
                               const float* __restrict__ ew) {
    int e = blockIdx.x * blockDim.x + threadIdx.x;
    if (e < Ee) {
        unsigned r = (unsigned)rows[e];
        unsigned c = (unsigned)cols[e];
        if (r < Nn && c < Nn) {
            int p = atomicAdd(&g_cursor[c], 1);
            float nw = g_dinv[r] * ew[e] * g_dinv[c];
            g_csr[p] = make_int2((int)r, __float_as_int(nw));
        }
    }
}

// ---------------------------------------------------------------------------
// GEMM h0 = relu(x @ W0^T + b).  Also writes fp16 shadow for the gather.
// ---------------------------------------------------------------------------
__global__ void __launch_bounds__(256)
gemm_h0_kernel(const float* __restrict__ x, const float* __restrict__ w0,
               const float* __restrict__ b) {
    __shared__ __align__(16) float As[64][128];  // [k][node]
    __shared__ __align__(16) float Ws[64][64];   // [k][f]
    int t = threadIdx.x;
    int n0 = blockIdx.x * 128;

    for (int i = t; i < 4096; i += 256) {
        int k = i >> 6, f = i & 63;
        Ws[k][f] = w0[f * 64 + k];  // transpose: need W0[f][k] at [k][f]
    }
    for (int i = t * 4; i < 8192; i += 1024) {
        int node = i >> 6, k = i & 63;
        int gn = n0 + node;
        float4 v = make_float4(0.f, 0.f, 0.f, 0.f);
        if (gn < Nn) v = *(const float4*)(x + (size_t)gn * 64 + k);
        As[k + 0][node] = v.x; As[k + 1][node] = v.y;
        As[k + 2][node] = v.z; As[k + 3][node] = v.w;
    }
    __syncthreads();

    int tf = (t & 15) * 4;
    int tn = (t >> 4) * 8;
    float acc[8][4];
#pragma unroll
    for (int j = 0; j < 8; j++)
        acc[j][0] = acc[j][1] = acc[j][2] = acc[j][3] = 0.f;

#pragma unroll 8
    for (int k = 0; k < 64; k++) {
        float4 w4 = *(const float4*)&Ws[k][tf];
        float4 b0v = *(const float4*)&As[k][tn];
        float4 b1v = *(const float4*)&As[k][tn + 4];
        float a[8] = {b0v.x, b0v.y, b0v.z, b0v.w, b1v.x, b1v.y, b1v.z, b1v.w};
#pragma unroll
        for (int j = 0; j < 8; j++) {
            acc[j][0] = fmaf(a[j], w4.x, acc[j][0]);
            acc[j][1] = fmaf(a[j], w4.y, acc[j][1]);
            acc[j][2] = fmaf(a[j], w4.z, acc[j][2]);
            acc[j][3] = fmaf(a[j], w4.w, acc[j][3]);
        }
    }
    float4 bv = *(const float4*)(b + tf);
#pragma unroll
    for (int j = 0; j < 8; j++) {
        int gn = n0 + tn + j;
        if (gn < Nn) {
            float4 r;
            r.x = fmaxf(acc[j][0] + bv.x, 0.f);
            r.y = fmaxf(acc[j][1] + bv.y, 0.f);
            r.z = fmaxf(acc[j][2] + bv.z, 0.f);
            r.w = fmaxf(acc[j][3] + bv.w, 0.f);
            *(float4*)&g_h0[(size_t)gn * 64 + tf] = r;
            __half2 p0 = __floats2half2_rn(r.x, r.y);
            __half2 p1 = __floats2half2_rn(r.z, r.w);
            *(__half2*)&g_h16[(size_t)gn * 64 + tf] = p0;
            *(__half2*)&g_h16[(size_t)gn * 64 + tf + 2] = p1;
        }
    }
}

// ---------------------------------------------------------------------------
// FUSED gather + conv GEMM:
//   phase 1: per-warp CSR gather (fp16 src) -> mix 0.1*agg + 0.9*h0 -> smem Bs
//   phase 2: Bs @ W1 -> out = prev + relu(.)
// layer 0: src=g_h16, prev=h0,   out=g_out1 (+ fp16 shadow g_o16)
// layer 1: src=g_o16, prev=out1, out=d_out
// ---------------------------------------------------------------------------
__global__ void __launch_bounds__(256)
fused_conv_kernel(const float* __restrict__ w1, int layer,
                  float* __restrict__ dout) {
    __shared__ __align__(16) float Bs[128][64];  // node-major mixed features
    __shared__ __align__(16) float Ws[64][64];   // [k][f]
    int t = threadIdx.x;
    int warp = t >> 5;
    int lane = t & 31;
    int n0 = blockIdx.x * 128;
    const __half* __restrict__ hsrc = layer ? g_o16 : g_h16;
    const float* __restrict__ prev = layer ? g_out1 : g_h0;
    float* __restrict__ out = layer ? dout : g_out1;

    for (int i = t; i < 4096; i += 256)
        Ws[i >> 6][i & 63] = w1[i];

    // ---- phase 1: gather 16 nodes per warp ----
    for (int i = 0; i < 16; i++) {
        int ln = warp * 16 + i;
        int gn = n0 + ln;
        float2 v = make_float2(0.f, 0.f);
        if (gn < Nn) {
            int beg = g_off[gn];
            int end = beg + g_cnt[gn];
            float2 a0 = make_float2(0.f, 0.f);
            float2 a1 = make_float2(0.f, 0.f);
            float2 a2 = make_float2(0.f, 0.f);
            float2 a3 = make_float2(0.f, 0.f);
            int j = beg;
            for (; j + 4 <= end; j += 4) {
                int2 c0 = g_csr[j];
                int2 c1 = g_csr[j + 1];
                int2 c2 = g_csr[j + 2];
                int2 c3 = g_csr[j + 3];
                float2 v0 = __half22float2(*(const __half2*)(hsrc + (size_t)c0.x * Ff + lane * 2));
                float2 v1 = __half22float2(*(const __half2*)(hsrc + (size_t)c1.x * Ff + lane * 2));
                float2 v2 = __half22float2(*(const __half2*)(hsrc + (size_t)c2.x * Ff + lane * 2));
                float2 v3 = __half22float2(*(const __half2*)(hsrc + (size_t)c3.x * Ff + lane * 2));
                float w0 = __int_as_float(c0.y), w1f = __int_as_float(c1.y);
                float w2 = __int_as_float(c2.y), w3f = __int_as_float(c3.y);
                a0.x = fmaf(w0, v0.x, a0.x);  a0.y = fmaf(w0, v0.y, a0.y);
                a1.x = fmaf(w1f, v1.x, a1.x); a1.y = fmaf(w1f, v1.y, a1.y);
                a2.x = fmaf(w2, v2.x, a2.x);  a2.y = fmaf(w2, v2.y, a2.y);
                a3.x = fmaf(w3f, v3.x, a3.x); a3.y = fmaf(w3f, v3.y, a3.y);
            }
            for (; j < end; j++) {
                int2 c0 = g_csr[j];
                float2 v0 = __half22float2(*(const __half2*)(hsrc + (size_t)c0.x * Ff + lane * 2));
                float w0 = __int_as_float(c0.y);
                a0.x = fmaf(w0, v0.x, a0.x); a0.y = fmaf(w0, v0.y, a0.y);
            }
            a0.x += a1.x + a2.x + a3.x;
            a0.y += a1.y + a2.y + a3.y;
            float2 h = *(const float2*)(g_h0 + (size_t)gn * Ff + lane * 2);
            v.x = fmaf(0.1f, a0.x, 0.9f * h.x);
            v.y = fmaf(0.1f, a0.y, 0.9f * h.y);
        }
        *(float2*)&Bs[ln][lane * 2] = v;
    }
    __syncthreads();

    // ---- phase 2: GEMM Bs @ W1 + epilogue ----
    int tf = (t & 15) * 4;
    int tn = (t >> 4) * 8;
    float acc[8][4];
#pragma unroll
    for (int j = 0; j < 8; j++)
        acc[j][0] = acc[j][1] = acc[j][2] = acc[j][3] = 0.f;

#pragma unroll 8
    for (int k = 0; k < 64; k++) {
        float4 w4 = *(const float4*)&Ws[k][tf];
        float a[8];
#pragma unroll
        for (int j = 0; j < 8; j++) a[j] = Bs[tn + j][k];
#pragma unroll
        for (int j = 0; j < 8; j++) {
            acc[j][0] = fmaf(a[j], w4.x, acc[j][0]);
            acc[j][1] = fmaf(a[j], w4.y, acc[j][1]);
            acc[j][2] = fmaf(a[j], w4.z, acc[j][2]);
            acc[j][3] = fmaf(a[j], w4.w, acc[j][3]);
        }
    }
#pragma unroll
    for (int j = 0; j < 8; j++) {
        int gn = n0 + tn + j;
        if (gn < Nn) {
            float4 p = *(const float4*)(prev + (size_t)gn * 64 + tf);
            float4 r;
            r.x = p.x + fmaxf(acc[j][0], 0.f);
            r.y = p.y + fmaxf(acc[j][1], 0.f);
            r.z = p.z + fmaxf(acc[j][2], 0.f);
            r.w = p.w + fmaxf(acc[j][3], 0.f);
            *(float4*)(out + (size_t)gn * 64 + tf) = r;
            if (layer == 0) {
                __half2 p0 = __floats2half2_rn(r.x, r.y);
                __half2 p1 = __floats2half2_rn(r.z, r.w);
                *(__half2*)&g_o16[(size_t)gn * 64 + tf] = p0;
                *(__half2*)&g_o16[(size_t)gn * 64 + tf + 2] = p1;
            }
        }
    }
}

// ---------------------------------------------------------------------------
extern "C" void kernel_launch(void* const* d_in, const int* in_sizes, int n_in,
                              void* d_out, int out_size) {
    const float* x  = (const float*)d_in[0];
    const int*   ei = (const int*)d_in[1];   // int32 (harness: int64 -> int32)
    const float* ew = (const float*)d_in[2];
    // d_in[3] = edge_attr (unused by the module)
    const float* w0 = (const float*)d_in[4];
    const float* b0 = (const float*)d_in[5];
    const float* w1 = (const float*)d_in[6];
    float* out = (float*)d_out;

    const int* rows = ei;
    const int* cols = ei + Ee;

    const int EB = (Ee + 255) / 256;
    const int NB = (Nn + 255) / 256;
    const int GB = (Nn + 127) / 128;

    static cudaStream_t s1 = nullptr;
    static cudaEvent_t ev_fork = nullptr, ev_join = nullptr;
    if (s1 == nullptr) {
        cudaStreamCreateWithFlags(&s1, cudaStreamNonBlocking);
        cudaEventCreateWithFlags(&ev_fork, cudaEventDisableTiming);
        cudaEventCreateWithFlags(&ev_join, cudaEventDisableTiming);
    }

    // Fork: gemm_h0 is independent of the CSR build chain.
    cudaEventRecord(ev_fork, 0);
    cudaStreamWaitEvent(s1, ev_fork, 0);
    gemm_h0_kernel<<<GB, 256, 0, s1>>>(x, w0, b0);
    cudaEventRecord(ev_join, s1);

    // CSR build chain on the main stream.
    zero_kernel<<<NB, 256>>>();
    deg_kernel<<<EB, 256>>>(cols, ew);
    scan_sum_kernel<<<SCAN_B, 1024>>>();
    scan_base_kernel<<<1, 128>>>();
    scan_final_kernel<<<SCAN_B, 1024>>>();   // also computes dinv
    scatter_kernel<<<EB, 256>>>(rows, cols, ew);

    // Join: fused conv needs both h0 and the CSR.
    cudaStreamWaitEvent(0, ev_join, 0);

    fused_conv_kernel<<<GB, 256>>>(w1, 0, out);            // layer 1
    fused_conv_kernel<<<GB, 256>>>(w1 + 64 * 64, 1, out);  // layer 2
}

// round 9
// speedup vs baseline: 1.1092x; 1.1092x over previous
#include <cuda_runtime.h>
#include <cuda_fp16.h>
#include <mma.h>

using namespace nvcuda;

#define Nn 100000
#define Ff 64
#define Ee 1600000
#define SCAN_B 98   // ceil(Nn/1024)

// Scratch (device globals — no allocation allowed anywhere)
__device__ float  g_deg[Nn];
__device__ float  g_dinv[Nn];
__device__ int    g_cnt[Nn];
__device__ int    g_off[Nn];
__device__ int    g_cursor[Nn];
__device__ int    g_bsum[128];
__device__ int    g_bbase[128];
__device__ int2   g_csr[Ee];          // (row, __float_as_int(nw))
__device__ float  g_h0[(size_t)Nn * Ff];
__device__ float  g_out1[(size_t)Nn * Ff];
__device__ __half g_h16[(size_t)Nn * Ff];    // fp16 shadow of h0   (gather src)
__device__ __half g_o16[(size_t)Nn * Ff];    // fp16 shadow of out1 (gather src)
__device__ __half g_agg16[(size_t)Nn * Ff];  // fp16 aggregate

// ---------------------------------------------------------------------------
__global__ void zero_kernel() {
    int i = blockIdx.x * blockDim.x + threadIdx.x;
    if (i < Nn) { g_deg[i] = 0.f; g_cnt[i] = 0; }
}

// ---------------------------------------------------------------------------
__global__ void deg_kernel(const int* __restrict__ cols,
                           const float* __restrict__ ew) {
    int e = blockIdx.x * blockDim.x + threadIdx.x;
    if (e < Ee) {
        unsigned c = (unsigned)cols[e];
        if (c < Nn) {
            atomicAdd(&g_deg[c], ew[e]);
            atomicAdd(&g_cnt[c], 1);
        }
    }
}

// ---------------------------------------------------------------------------
// 3-phase exclusive scan of g_cnt -> g_off/g_cursor (+ dinv fused in phase 3)
// ---------------------------------------------------------------------------
__global__ void __launch_bounds__(1024)
scan_sum_kernel() {
    __shared__ int sm[1024];
    int t = threadIdx.x;
    int i = blockIdx.x * 1024 + t;
    sm[t] = (i < Nn) ? g_cnt[i] : 0;
    __syncthreads();
    for (int d = 512; d > 0; d >>= 1) {
        if (t < d) sm[t] += sm[t + d];
        __syncthreads();
    }
    if (t == 0) g_bsum[blockIdx.x] = sm[0];
}

__global__ void __launch_bounds__(128)
scan_base_kernel() {
    __shared__ int sm[128];
    int t = threadIdx.x;
    int v = (t < SCAN_B) ? g_bsum[t] : 0;
    sm[t] = v;
    __syncthreads();
    for (int d = 1; d < 128; d <<= 1) {
        int u = (t >= d) ? sm[t - d] : 0;
        __syncthreads();
        sm[t] += u;
        __syncthreads();
    }
    if (t < SCAN_B) g_bbase[t] = sm[t] - v;  // exclusive
}

__global__ void __launch_bounds__(1024)
scan_final_kernel() {
    __shared__ int sm[1024];
    int t = threadIdx.x;
    int i = blockIdx.x * 1024 + t;
    int v = (i < Nn) ? g_cnt[i] : 0;
    sm[t] = v;
    __syncthreads();
    for (int d = 1; d < 1024; d <<= 1) {
        int u = (t >= d) ? sm[t - d] : 0;
        __syncthreads();
        sm[t] += u;
        __syncthreads();
    }
    if (i < Nn) {
        int off = g_bbase[blockIdx.x] + sm[t] - v;
        g_off[i] = off;
        g_cursor[i] = off;
        float d = g_deg[i];                      // dinv fused here
        g_dinv[i] = d > 0.f ? rsqrtf(d) : 0.f;
    }
}

// ---------------------------------------------------------------------------
// Scatter edges into packed CSR slots (one 8B write per edge).
// ---------------------------------------------------------------------------
__global__ void scatter_kernel(const int* __restrict__ rows,
                               const int* __restrict__ cols,
                               const float* __restrict__ ew) {
    int e = blockIdx.x * blockDim.x + threadIdx.x;
    if (e < Ee) {
        unsigned r = (unsigned)rows[e];
        unsigned c = (unsigned)cols[e];
        if (r < Nn && c < Nn) {
            int p = atomicAdd(&g_cursor[c], 1);
            float nw = g_dinv[r] * ew[e] * g_dinv[c];
            g_csr[p] = make_int2((int)r, __float_as_int(nw));
        }
    }
}

// ---------------------------------------------------------------------------
// SpMM gather (fp16 src, fp16 dst): agg16[n] = sum nw * h16[row].
// One warp per node, lane owns 2 feats.
// ---------------------------------------------------------------------------
__global__ void __launch_bounds__(256)
gather_kernel(int src) {
    int w = (blockIdx.x * 256 + threadIdx.x) >> 5;   // node id
    int lane = threadIdx.x & 31;
    if (w >= Nn) return;
    const __half* __restrict__ h = src ? g_o16 : g_h16;
    int beg = g_off[w];
    int end = beg + g_cnt[w];
    float2 a0 = make_float2(0.f, 0.f);
    float2 a1 = make_float2(0.f, 0.f);
    float2 a2 = make_float2(0.f, 0.f);
    float2 a3 = make_float2(0.f, 0.f);
    int j = beg;
    for (; j + 4 <= end; j += 4) {
        int2 c0 = g_csr[j];
        int2 c1 = g_csr[j + 1];
        int2 c2 = g_csr[j + 2];
        int2 c3 = g_csr[j + 3];
        float2 v0 = __half22float2(*(const __half2*)(h + (size_t)c0.x * Ff + lane * 2));
        float2 v1 = __half22float2(*(const __half2*)(h + (size_t)c1.x * Ff + lane * 2));
        float2 v2 = __half22float2(*(const __half2*)(h + (size_t)c2.x * Ff + lane * 2));
        float2 v3 = __half22float2(*(const __half2*)(h + (size_t)c3.x * Ff + lane * 2));
        float w0 = __int_as_float(c0.y), w1 = __int_as_float(c1.y);
        float w2 = __int_as_float(c2.y), w3 = __int_as_float(c3.y);
        a0.x = fmaf(w0, v0.x, a0.x); a0.y = fmaf(w0, v0.y, a0.y);
        a1.x = fmaf(w1, v1.x, a1.x); a1.y = fmaf(w1, v1.y, a1.y);
        a2.x = fmaf(w2, v2.x, a2.x); a2.y = fmaf(w2, v2.y, a2.y);
        a3.x = fmaf(w3, v3.x, a3.x); a3.y = fmaf(w3, v3.y, a3.y);
    }
    for (; j < end; j++) {
        int2 c0 = g_csr[j];
        float2 v0 = __half22float2(*(const __half2*)(h + (size_t)c0.x * Ff + lane * 2));
        float w0 = __int_as_float(c0.y);
        a0.x = fmaf(w0, v0.x, a0.x); a0.y = fmaf(w0, v0.y, a0.y);
    }
    a0.x += a1.x + a2.x + a3.x;
    a0.y += a1.y + a2.y + a3.y;
    *(__half2*)(g_agg16 + (size_t)w * Ff + lane * 2) = __floats2half2_rn(a0.x, a0.y);
}

// ---------------------------------------------------------------------------
// GEMM h0 = relu(x @ W0^T + b).  f32 FFMA (fully overlapped with CSR build).
// Also writes fp16 shadow for the gather.
// ---------------------------------------------------------------------------
__global__ void __launch_bounds__(256)
gemm_h0_kernel(const float* __restrict__ x, const float* __restrict__ w0,
               const float* __restrict__ b) {
    __shared__ __align__(16) float As[64][128];  // [k][node]
    __shared__ __align__(16) float Ws[64][64];   // [k][f]
    int t = threadIdx.x;
    int n0 = blockIdx.x * 128;

    for (int i = t; i < 4096; i += 256) {
        int k = i >> 6, f = i & 63;
        Ws[k][f] = w0[f * 64 + k];  // transpose: need W0[f][k] at [k][f]
    }
    for (int i = t * 4; i < 8192; i += 1024) {
        int node = i >> 6, k = i & 63;
        int gn = n0 + node;
        float4 v = make_float4(0.f, 0.f, 0.f, 0.f);
        if (gn < Nn) v = *(const float4*)(x + (size_t)gn * 64 + k);
        As[k + 0][node] = v.x; As[k + 1][node] = v.y;
        As[k + 2][node] = v.z; As[k + 3][node] = v.w;
    }
    __syncthreads();

    int tf = (t & 15) * 4;
    int tn = (t >> 4) * 8;
    float acc[8][4];
#pragma unroll
    for (int j = 0; j < 8; j++)
        acc[j][0] = acc[j][1] = acc[j][2] = acc[j][3] = 0.f;

#pragma unroll 8
    for (int k = 0; k < 64; k++) {
        float4 w4 = *(const float4*)&Ws[k][tf];
        float4 b0v = *(const float4*)&As[k][tn];
        float4 b1v = *(const float4*)&As[k][tn + 4];
        float a[8] = {b0v.x, b0v.y, b0v.z, b0v.w, b1v.x, b1v.y, b1v.z, b1v.w};
#pragma unroll
        for (int j = 0; j < 8; j++) {
            acc[j][0] = fmaf(a[j], w4.x, acc[j][0]);
            acc[j][1] = fmaf(a[j], w4.y, acc[j][1]);
            acc[j][2] = fmaf(a[j], w4.z, acc[j][2]);
            acc[j][3] = fmaf(a[j], w4.w, acc[j][3]);
        }
    }
    float4 bv = *(const float4*)(b + tf);
#pragma unroll
    for (int j = 0; j < 8; j++) {
        int gn = n0 + tn + j;
        if (gn < Nn) {
            float4 r;
            r.x = fmaxf(acc[j][0] + bv.x, 0.f);
            r.y = fmaxf(acc[j][1] + bv.y, 0.f);
            r.z = fmaxf(acc[j][2] + bv.z, 0.f);
            r.w = fmaxf(acc[j][3] + bv.w, 0.f);
            *(float4*)&g_h0[(size_t)gn * 64 + tf] = r;
            __half2 p0 = __floats2half2_rn(r.x, r.y);
            __half2 p1 = __floats2half2_rn(r.z, r.w);
            *(__half2*)&g_h16[(size_t)gn * 64 + tf] = p0;
            *(__half2*)&g_h16[(size_t)gn * 64 + tf + 2] = p1;
        }
    }
}

// ---------------------------------------------------------------------------
// Conv GEMM via wmma tf32: out = prev + relu( (0.1*agg16 + 0.9*h16) @ W1 )
// 128x64 tile per block, 8 warps, each warp computes 16 rows x 64 cols.
// ---------------------------------------------------------------------------
__global__ void __launch_bounds__(256)
conv_wmma_kernel(const float* __restrict__ w1, int layer,
                 float* __restrict__ dout) {
    __shared__ __align__(16) float Amix[128][64];  // mixed input, later acc
    __shared__ __align__(16) float Wsm[64][64];    // W1 [k][f]
    int t = threadIdx.x;
    int warp = t >> 5;
    int lane = t & 31;
    int n0 = blockIdx.x * 128;
    const float* __restrict__ prev = layer ? g_out1 : g_h0;
    float* __restrict__ out = layer ? dout : g_out1;

    for (int i = t; i < 4096; i += 256)
        Wsm[i >> 6][i & 63] = w1[i];

    // Build mix tile from fp16 agg + fp16 h0 shadow.
    for (int i = t; i < 128 * 32; i += 256) {
        int row = i >> 5, p = i & 31;
        int gn = n0 + row;
        float mx = 0.f, my = 0.f;
        if (gn < Nn) {
            float2 a = __half22float2(*(const __half2*)(g_agg16 + (size_t)gn * 64 + p * 2));
            float2 h = __half22float2(*(const __half2*)(g_h16 + (size_t)gn * 64 + p * 2));
            mx = fmaf(0.1f, a.x, 0.9f * h.x);
            my = fmaf(0.1f, a.y, 0.9f * h.y);
        }
        Amix[row][p * 2] = mx;
        Amix[row][p * 2 + 1] = my;
    }
    __syncthreads();

    // Tensor-core GEMM: each warp does rows [16*warp, 16*warp+16) x all 64 cols.
    wmma::fragment<wmma::accumulator, 16, 16, 8, float> c[4];
#pragma unroll
    for (int n = 0; n < 4; n++) wmma::fill_fragment(c[n], 0.f);

#pragma unroll
    for (int ks = 0; ks < 8; ks++) {
        wmma::fragment<wmma::matrix_a, 16, 16, 8, wmma::precision::tf32, wmma::row_major> af;
        wmma::load_matrix_sync(af, &Amix[warp * 16][ks * 8], 64);
#pragma unroll
        for (int i = 0; i < af.num_elements; i++)
            af.x[i] = wmma::__float_to_tf32(af.x[i]);
#pragma unroll
        for (int n = 0; n < 4; n++) {
            wmma::fragment<wmma::matrix_b, 16, 16, 8, wmma::precision::tf32, wmma::row_major> bf;
            wmma::load_matrix_sync(bf, &Wsm[ks * 8][n * 16], 64);
#pragma unroll
            for (int i = 0; i < bf.num_elements; i++)
                bf.x[i] = wmma::__float_to_tf32(bf.x[i]);
            wmma::mma_sync(c[n], af, bf, c[n]);
        }
    }

    // Each warp overwrites only its own 16 rows of Amix — no cross-warp hazard.
#pragma unroll
    for (int n = 0; n < 4; n++)
        wmma::store_matrix_sync(&Amix[warp * 16][n * 16], c[n], 64, wmma::mem_row_major);
    __syncwarp();

    // Epilogue: out = prev + relu(acc); layer 0 also writes fp16 shadow.
#pragma unroll
    for (int r = 0; r < 16; r++) {
        int gn = n0 + warp * 16 + r;
        if (gn < Nn) {
            float2 v = *(const float2*)&Amix[warp * 16 + r][lane * 2];
            float2 p = *(const float2*)(prev + (size_t)gn * 64 + lane * 2);
            float2 o;
            o.x = p.x + fmaxf(v.x, 0.f);
            o.y = p.y + fmaxf(v.y, 0.f);
            *(float2*)(out + (size_t)gn * 64 + lane * 2) = o;
            if (layer == 0)
                *(__half2*)(g_o16 + (size_t)gn * 64 + lane * 2) = __floats2half2_rn(o.x, o.y);
        }
    }
}

// ---------------------------------------------------------------------------
extern "C" void kernel_launch(void* const* d_in, const int* in_sizes, int n_in,
                              void* d_out, int out_size) {
    const float* x  = (const float*)d_in[0];
    const int*   ei = (const int*)d_in[1];   // int32 (harness: int64 -> int32)
    const float* ew = (const float*)d_in[2];
    // d_in[3] = edge_attr (unused by the module)
    const float* w0 = (const float*)d_in[4];
    const float* b0 = (const float*)d_in[5];
    const float* w1 = (const float*)d_in[6];
    float* out = (float*)d_out;

    const int* rows = ei;
    const int* cols = ei + Ee;

    const int EB = (Ee + 255) / 256;
    const int NB = (Nn + 255) / 256;
    const int GB = (Nn + 127) / 128;
    const int WB = (Nn + 7) / 8;

    static cudaStream_t s1 = nullptr;
    static cudaEvent_t ev_fork = nullptr, ev_join = nullptr;
    if (s1 == nullptr) {
        cudaStreamCreateWithFlags(&s1, cudaStreamNonBlocking);
        cudaEventCreateWithFlags(&ev_fork, cudaEventDisableTiming);
        cudaEventCreateWithFlags(&ev_join, cudaEventDisableTiming);
    }

    // Fork: gemm_h0 is independent of the CSR build chain.
    cudaEventRecord(ev_fork, 0);
    cudaStreamWaitEvent(s1, ev_fork, 0);
    gemm_h0_kernel<<<GB, 256, 0, s1>>>(x, w0, b0);
    cudaEventRecord(ev_join, s1);

    // CSR build chain on the main stream.
    zero_kernel<<<NB, 256>>>();
    deg_kernel<<<EB, 256>>>(cols, ew);
    scan_sum_kernel<<<SCAN_B, 1024>>>();
    scan_base_kernel<<<1, 128>>>();
    scan_final_kernel<<<SCAN_B, 1024>>>();   // also computes dinv
    scatter_kernel<<<EB, 256>>>(rows, cols, ew);

    // Join: gather needs both h0 and the CSR.
    cudaStreamWaitEvent(0, ev_join, 0);

    // layer 1
    gather_kernel<<<WB, 256>>>(0);
    conv_wmma_kernel<<<GB, 256>>>(w1, 0, out);

    // layer 2
    gather_kernel<<<WB, 256>>>(1);
    conv_wmma_kernel<<<GB, 256>>>(w1 + 64 * 64, 1, out);
}

// round 10
// speedup vs baseline: 1.2497x; 1.1266x over previous
#include <cuda_runtime.h>
#include <cuda_fp16.h>

#define Nn 100000
#define Ff 64
#define Ee 1600000
#define SCAN_B 98   // ceil(Nn/1024)

// Scratch (device globals — no allocation allowed anywhere)
__device__ float  g_deg[Nn];
__device__ float  g_dinv[Nn];
__device__ int    g_cnt[Nn];
__device__ int    g_off[Nn];
__device__ int    g_cursor[Nn];
__device__ int    g_bsum[128];
__device__ int    g_bbase[128];
__device__ int2   g_csr[Ee];          // (row, __float_as_int(nw))
__device__ float  g_h0[(size_t)Nn * Ff];
__device__ float  g_out1[(size_t)Nn * Ff];
__device__ __half g_h16[(size_t)Nn * Ff];    // fp16 shadow of h0   (gather src)
__device__ __half g_o16[(size_t)Nn * Ff];    // fp16 shadow of out1 (gather src)
__device__ __half g_agg16[(size_t)Nn * Ff];  // fp16 aggregate

// ---------------------------------------------------------------------------
__global__ void zero_kernel() {
    int i = blockIdx.x * blockDim.x + threadIdx.x;
    if (i < Nn) { g_deg[i] = 0.f; g_cnt[i] = 0; }
}

// ---------------------------------------------------------------------------
// deg[col[e]] += w[e];  cnt[col[e]] += 1     (2 edges per thread, int2 loads)
// ---------------------------------------------------------------------------
__global__ void deg_kernel(const int* __restrict__ cols,
                           const float* __restrict__ ew) {
    int e2 = blockIdx.x * blockDim.x + threadIdx.x;   // edge-pair index
    if (e2 * 2 + 1 < Ee) {
        int2 c = *(const int2*)(cols + e2 * 2);
        float2 w = *(const float2*)(ew + e2 * 2);
        if ((unsigned)c.x < Nn) {
            atomicAdd(&g_deg[c.x], w.x);
            atomicAdd(&g_cnt[c.x], 1);
        }
        if ((unsigned)c.y < Nn) {
            atomicAdd(&g_deg[c.y], w.y);
            atomicAdd(&g_cnt[c.y], 1);
        }
    } else if (e2 * 2 < Ee) {
        int c = cols[e2 * 2];
        if ((unsigned)c < Nn) {
            atomicAdd(&g_deg[c], ew[e2 * 2]);
            atomicAdd(&g_cnt[c], 1);
        }
    }
}

// ---------------------------------------------------------------------------
// 3-phase exclusive scan of g_cnt -> g_off/g_cursor (+ dinv fused in phase 3)
// ---------------------------------------------------------------------------
__global__ void __launch_bounds__(1024)
scan_sum_kernel() {
    __shared__ int sm[1024];
    int t = threadIdx.x;
    int i = blockIdx.x * 1024 + t;
    sm[t] = (i < Nn) ? g_cnt[i] : 0;
    __syncthreads();
    for (int d = 512; d > 0; d >>= 1) {
        if (t < d) sm[t] += sm[t + d];
        __syncthreads();
    }
    if (t == 0) g_bsum[blockIdx.x] = sm[0];
}

__global__ void __launch_bounds__(128)
scan_base_kernel() {
    __shared__ int sm[128];
    int t = threadIdx.x;
    int v = (t < SCAN_B) ? g_bsum[t] : 0;
    sm[t] = v;
    __syncthreads();
    for (int d = 1; d < 128; d <<= 1) {
        int u = (t >= d) ? sm[t - d] : 0;
        __syncthreads();
        sm[t] += u;
        __syncthreads();
    }
    if (t < SCAN_B) g_bbase[t] = sm[t] - v;  // exclusive
}

__global__ void __launch_bounds__(1024)
scan_final_kernel() {
    __shared__ int sm[1024];
    int t = threadIdx.x;
    int i = blockIdx.x * 1024 + t;
    int v = (i < Nn) ? g_cnt[i] : 0;
    sm[t] = v;
    __syncthreads();
    for (int d = 1; d < 1024; d <<= 1) {
        int u = (t >= d) ? sm[t - d] : 0;
        __syncthreads();
        sm[t] += u;
        __syncthreads();
    }
    if (i < Nn) {
        int off = g_bbase[blockIdx.x] + sm[t] - v;
        g_off[i] = off;
        g_cursor[i] = off;
        float d = g_deg[i];                      // dinv fused here
        g_dinv[i] = d > 0.f ? rsqrtf(d) : 0.f;
    }
}

// ---------------------------------------------------------------------------
// Scatter edges into packed CSR slots (2 edges/thread, one 8B write per edge).
// ---------------------------------------------------------------------------
__global__ void scatter_kernel(const int* __restrict__ rows,
                               const int* __restrict__ cols,
                               const float* __restrict__ ew) {
    int e2 = blockIdx.x * blockDim.x + threadIdx.x;
    if (e2 * 2 + 1 < Ee) {
        int2 r = *(const int2*)(rows + e2 * 2);
        int2 c = *(const int2*)(cols + e2 * 2);
        float2 w = *(const float2*)(ew + e2 * 2);
        if ((unsigned)r.x < Nn && (unsigned)c.x < Nn) {
            int p = atomicAdd(&g_cursor[c.x], 1);
            g_csr[p] = make_int2(r.x, __float_as_int(g_dinv[r.x] * w.x * g_dinv[c.x]));
        }
        if ((unsigned)r.y < Nn && (unsigned)c.y < Nn) {
            int p = atomicAdd(&g_cursor[c.y], 1);
            g_csr[p] = make_int2(r.y, __float_as_int(g_dinv[r.y] * w.y * g_dinv[c.y]));
        }
    } else if (e2 * 2 < Ee) {
        int r = rows[e2 * 2], c = cols[e2 * 2];
        if ((unsigned)r < Nn && (unsigned)c < Nn) {
            int p = atomicAdd(&g_cursor[c], 1);
            g_csr[p] = make_int2(r, __float_as_int(g_dinv[r] * ew[e2 * 2] * g_dinv[c]));
        }
    }
}

// ---------------------------------------------------------------------------
// SpMM gather (fp16 src, fp16 dst): agg16[n] = sum nw * h16[row].
// One warp per node, lane owns 2 feats. 4 independent streams for MLP.
// ---------------------------------------------------------------------------
__global__ void __launch_bounds__(256)
gather_kernel(int src) {
    int w = (blockIdx.x * 256 + threadIdx.x) >> 5;   // node id
    int lane = threadIdx.x & 31;
    if (w >= Nn) return;
    const __half* __restrict__ h = src ? g_o16 : g_h16;
    int beg = g_off[w];
    int end = beg + g_cnt[w];
    float2 a0 = make_float2(0.f, 0.f);
    float2 a1 = make_float2(0.f, 0.f);
    float2 a2 = make_float2(0.f, 0.f);
    float2 a3 = make_float2(0.f, 0.f);
    int j = beg;
    for (; j + 4 <= end; j += 4) {
        int2 c0 = g_csr[j];
        int2 c1 = g_csr[j + 1];
        int2 c2 = g_csr[j + 2];
        int2 c3 = g_csr[j + 3];
        float2 v0 = __half22float2(*(const __half2*)(h + (size_t)c0.x * Ff + lane * 2));
        float2 v1 = __half22float2(*(const __half2*)(h + (size_t)c1.x * Ff + lane * 2));
        float2 v2 = __half22float2(*(const __half2*)(h + (size_t)c2.x * Ff + lane * 2));
        float2 v3 = __half22float2(*(const __half2*)(h + (size_t)c3.x * Ff + lane * 2));
        float w0 = __int_as_float(c0.y), w1 = __int_as_float(c1.y);
        float w2 = __int_as_float(c2.y), w3 = __int_as_float(c3.y);
        a0.x = fmaf(w0, v0.x, a0.x); a0.y = fmaf(w0, v0.y, a0.y);
        a1.x = fmaf(w1, v1.x, a1.x); a1.y = fmaf(w1, v1.y, a1.y);
        a2.x = fmaf(w2, v2.x, a2.x); a2.y = fmaf(w2, v2.y, a2.y);
        a3.x = fmaf(w3, v3.x, a3.x); a3.y = fmaf(w3, v3.y, a3.y);
    }
    for (; j < end; j++) {
        int2 c0 = g_csr[j];
        float2 v0 = __half22float2(*(const __half2*)(h + (size_t)c0.x * Ff + lane * 2));
        float w0 = __int_as_float(c0.y);
        a0.x = fmaf(w0, v0.x, a0.x); a0.y = fmaf(w0, v0.y, a0.y);
    }
    a0.x += a1.x + a2.x + a3.x;
    a0.y += a1.y + a2.y + a3.y;
    *(__half2*)(g_agg16 + (size_t)w * Ff + lane * 2) = __floats2half2_rn(a0.x, a0.y);
}

// ---------------------------------------------------------------------------
// GEMM h0 = relu(x @ W0^T + b).  Also writes fp16 shadow for the gather.
// ---------------------------------------------------------------------------
__global__ void __launch_bounds__(256)
gemm_h0_kernel(const float* __restrict__ x, const float* __restrict__ w0,
               const float* __restrict__ b) {
    __shared__ __align__(16) float As[64][128];  // [k][node]
    __shared__ __align__(16) float Ws[64][64];   // [k][f]
    int t = threadIdx.x;
    int n0 = blockIdx.x * 128;

    for (int i = t; i < 4096; i += 256) {
        int k = i >> 6, f = i & 63;
        Ws[k][f] = w0[f * 64 + k];  // transpose: need W0[f][k] at [k][f]
    }
    for (int i = t * 4; i < 8192; i += 1024) {
        int node = i >> 6, k = i & 63;
        int gn = n0 + node;
        float4 v = make_float4(0.f, 0.f, 0.f, 0.f);
        if (gn < Nn) v = *(const float4*)(x + (size_t)gn * 64 + k);
        As[k + 0][node] = v.x; As[k + 1][node] = v.y;
        As[k + 2][node] = v.z; As[k + 3][node] = v.w;
    }
    __syncthreads();

    int tf = (t & 15) * 4;
    int tn = (t >> 4) * 8;
    float acc[8][4];
#pragma unroll
    for (int j = 0; j < 8; j++)
        acc[j][0] = acc[j][1] = acc[j][2] = acc[j][3] = 0.f;

#pragma unroll 8
    for (int k = 0; k < 64; k++) {
        float4 w4 = *(const float4*)&Ws[k][tf];
        float4 b0v = *(const float4*)&As[k][tn];
        float4 b1v = *(const float4*)&As[k][tn + 4];
        float a[8] = {b0v.x, b0v.y, b0v.z, b0v.w, b1v.x, b1v.y, b1v.z, b1v.w};
#pragma unroll
        for (int j = 0; j < 8; j++) {
            acc[j][0] = fmaf(a[j], w4.x, acc[j][0]);
            acc[j][1] = fmaf(a[j], w4.y, acc[j][1]);
            acc[j][2] = fmaf(a[j], w4.z, acc[j][2]);
            acc[j][3] = fmaf(a[j], w4.w, acc[j][3]);
        }
    }
    float4 bv = *(const float4*)(b + tf);
#pragma unroll
    for (int j = 0; j < 8; j++) {
        int gn = n0 + tn + j;
        if (gn < Nn) {
            float4 r;
            r.x = fmaxf(acc[j][0] + bv.x, 0.f);
            r.y = fmaxf(acc[j][1] + bv.y, 0.f);
            r.z = fmaxf(acc[j][2] + bv.z, 0.f);
            r.w = fmaxf(acc[j][3] + bv.w, 0.f);
            *(float4*)&g_h0[(size_t)gn * 64 + tf] = r;
            __half2 p0 = __floats2half2_rn(r.x, r.y);
            __half2 p1 = __floats2half2_rn(r.z, r.w);
            *(__half2*)&g_h16[(size_t)gn * 64 + tf] = p0;
            *(__half2*)&g_h16[(size_t)gn * 64 + tf + 2] = p1;
        }
    }
}

// ---------------------------------------------------------------------------
// Fused conv GEMM: out = prev + relu( (0.1*agg16 + 0.9*h0) @ W1 )
// layer 0: prev = h0,   out = g_out1 (+ fp16 shadow g_o16)
// layer 1: prev = out1, out = d_out
// ---------------------------------------------------------------------------
__global__ void __launch_bounds__(256)
gemm_conv_kernel(const float* __restrict__ w1, int layer,
                 float* __restrict__ dout) {
    __shared__ __align__(16) float As[64][128];
    __shared__ __align__(16) float Ws[64][64];
    int t = threadIdx.x;
    int n0 = blockIdx.x * 128;
    const float* __restrict__ prev = layer ? g_out1 : g_h0;
    float* __restrict__ out = layer ? dout : g_out1;

    for (int i = t; i < 4096; i += 256) {
        Ws[i >> 6][i & 63] = w1[i];  // already [k][f]
    }
    for (int i = t * 4; i < 8192; i += 1024) {
        int node = i >> 6, k = i & 63;
        int gn = n0 + node;
        float4 v = make_float4(0.f, 0.f, 0.f, 0.f);
        if (gn < Nn) {
            float2 alo = __half22float2(*(const __half2*)(g_agg16 + (size_t)gn * 64 + k));
            float2 ahi = __half22float2(*(const __half2*)(g_agg16 + (size_t)gn * 64 + k + 2));
            float4 h = *(const float4*)(g_h0 + (size_t)gn * 64 + k);
            v.x = fmaf(0.1f, alo.x, 0.9f * h.x);
            v.y = fmaf(0.1f, alo.y, 0.9f * h.y);
            v.z = fmaf(0.1f, ahi.x, 0.9f * h.z);
            v.w = fmaf(0.1f, ahi.y, 0.9f * h.w);
        }
        As[k + 0][node] = v.x; As[k + 1][node] = v.y;
        As[k + 2][node] = v.z; As[k + 3][node] = v.w;
    }
    __syncthreads();

    int tf = (t & 15) * 4;
    int tn = (t >> 4) * 8;
    float acc[8][4];
#pragma unroll
    for (int j = 0; j < 8; j++)
        acc[j][0] = acc[j][1] = acc[j][2] = acc[j][3] = 0.f;

#pragma unroll 8
    for (int k = 0; k < 64; k++) {
        float4 w4 = *(const float4*)&Ws[k][tf];
        float4 b0v = *(const float4*)&As[k][tn];
        float4 b1v = *(const float4*)&As[k][tn + 4];
        float a[8] = {b0v.x, b0v.y, b0v.z, b0v.w, b1v.x, b1v.y, b1v.z, b1v.w};
#pragma unroll
        for (int j = 0; j < 8; j++) {
            acc[j][0] = fmaf(a[j], w4.x, acc[j][0]);
            acc[j][1] = fmaf(a[j], w4.y, acc[j][1]);
            acc[j][2] = fmaf(a[j], w4.z, acc[j][2]);
            acc[j][3] = fmaf(a[j], w4.w, acc[j][3]);
        }
    }
#pragma unroll
    for (int j = 0; j < 8; j++) {
        int gn = n0 + tn + j;
        if (gn < Nn) {
            float4 p = *(const float4*)(prev + (size_t)gn * 64 + tf);
            float4 r;
            r.x = p.x + fmaxf(acc[j][0], 0.f);
            r.y = p.y + fmaxf(acc[j][1], 0.f);
            r.z = p.z + fmaxf(acc[j][2], 0.f);
            r.w = p.w + fmaxf(acc[j][3], 0.f);
            *(float4*)(out + (size_t)gn * 64 + tf) = r;
            if (layer == 0) {
                __half2 p0 = __floats2half2_rn(r.x, r.y);
                __half2 p1 = __floats2half2_rn(r.z, r.w);
                *(__half2*)&g_o16[(size_t)gn * 64 + tf] = p0;
                *(__half2*)&g_o16[(size_t)gn * 64 + tf + 2] = p1;
            }
        }
    }
}

// ---------------------------------------------------------------------------
extern "C" void kernel_launch(void* const* d_in, const int* in_sizes, int n_in,
                              void* d_out, int out_size) {
    const float* x  = (const float*)d_in[0];
    const int*   ei = (const int*)d_in[1];   // int32 (harness: int64 -> int32)
    const float* ew = (const float*)d_in[2];
    // d_in[3] = edge_attr (unused by the module)
    const float* w0 = (const float*)d_in[4];
    const float* b0 = (const float*)d_in[5];
    const float* w1 = (const float*)d_in[6];
    float* out = (float*)d_out;

    const int* rows = ei;
    const int* cols = ei + Ee;

    const int E2B = (Ee / 2 + 255) / 256;   // 2 edges per thread
    const int NB = (Nn + 255) / 256;
    const int GB = (Nn + 127) / 128;
    const int WB = (Nn + 7) / 8;

    static cudaStream_t s1 = nullptr;
    static cudaEvent_t ev_fork = nullptr, ev_join = nullptr;
    if (s1 == nullptr) {
        cudaStreamCreateWithFlags(&s1, cudaStreamNonBlocking);
        cudaEventCreateWithFlags(&ev_fork, cudaEventDisableTiming);
        cudaEventCreateWithFlags(&ev_join, cudaEventDisableTiming);
    }

    // Fork: gemm_h0 is independent of the CSR build chain.
    cudaEventRecord(ev_fork, 0);
    cudaStreamWaitEvent(s1, ev_fork, 0);
    gemm_h0_kernel<<<GB, 256, 0, s1>>>(x, w0, b0);
    cudaEventRecord(ev_join, s1);

    // CSR build chain on the main stream.
    zero_kernel<<<NB, 256>>>();
    deg_kernel<<<E2B, 256>>>(cols, ew);
    scan_sum_kernel<<<SCAN_B, 1024>>>();
    scan_base_kernel<<<1, 128>>>();
    scan_final_kernel<<<SCAN_B, 1024>>>();   // also computes dinv
    scatter_kernel<<<E2B, 256>>>(rows, cols, ew);

    // Join: gather needs both h0 and the CSR.
    cudaStreamWaitEvent(0, ev_join, 0);

    // layer 1
    gather_kernel<<<WB, 256>>>(0);
    gemm_conv_kernel<<<GB, 256>>>(w1, 0, out);

    // layer 2
    gather_kernel<<<WB, 256>>>(1);
    gemm_conv_kernel<<<GB, 256>>>(w1 + 64 * 64, 1, out);
}

// round 11
// speedup vs baseline: 1.2650x; 1.0123x over previous
#include <cuda_runtime.h>
#include <cuda_fp16.h>

#define Nn 100000
#define Ff 64
#define Ee 1600000
#define SCAN_B 98   // ceil(Nn/1024)

typedef unsigned long long ull;

// Scratch (device globals — no allocation allowed anywhere)
__device__ float  g_deg[Nn];
__device__ float  g_dinv[Nn];
__device__ int    g_cnt[Nn];
__device__ int    g_off[Nn];
__device__ int    g_bsum[128];
__device__ int    g_bbase[128];
__device__ int    g_rank[Ee];         // per-edge rank within its column
__device__ int2   g_csr[Ee];          // (row, __float_as_int(nw))
__device__ float  g_h0[(size_t)Nn * Ff];
__device__ float  g_out1[(size_t)Nn * Ff];
__device__ __half g_h16[(size_t)Nn * Ff];    // fp16 shadow of h0   (gather src)
__device__ __half g_o16[(size_t)Nn * Ff];    // fp16 shadow of out1 (gather src)
__device__ __half g_agg16[(size_t)Nn * Ff];  // fp16 aggregate

// ---- packed f32x2 helpers (sm_103a FFMA2 — only reachable via PTX) --------
__device__ __forceinline__ ull fma2(ull a, ull b, ull c) {
    ull d;
    asm("fma.rn.f32x2 %0, %1, %2, %3;" : "=l"(d) : "l"(a), "l"(b), "l"(c));
    return d;
}
__device__ __forceinline__ ull dup2(float x) {
    ull d;
    asm("mov.b64 %0, {%1, %1};" : "=l"(d) : "f"(x));
    return d;
}
__device__ __forceinline__ void unpack2(ull v, float& lo, float& hi) {
    asm("mov.b64 {%0, %1}, %2;" : "=f"(lo), "=f"(hi) : "l"(v));
}

// ---------------------------------------------------------------------------
__global__ void zero_kernel() {
    int i = blockIdx.x * blockDim.x + threadIdx.x;
    if (i < Nn) { g_deg[i] = 0.f; g_cnt[i] = 0; }
}

// ---------------------------------------------------------------------------
// deg[col[e]] += w[e];  rank[e] = cnt[col[e]]++   (2 edges per thread)
// ---------------------------------------------------------------------------
__global__ void deg_kernel(const int* __restrict__ cols,
                           const float* __restrict__ ew) {
    int e2 = blockIdx.x * blockDim.x + threadIdx.x;   // edge-pair index
    if (e2 * 2 + 1 < Ee) {
        int2 c = *(const int2*)(cols + e2 * 2);
        float2 w = *(const float2*)(ew + e2 * 2);
        int r0 = 0, r1 = 0;
        if ((unsigned)c.x < Nn) {
            atomicAdd(&g_deg[c.x], w.x);
            r0 = atomicAdd(&g_cnt[c.x], 1);
        }
        if ((unsigned)c.y < Nn) {
            atomicAdd(&g_deg[c.y], w.y);
            r1 = atomicAdd(&g_cnt[c.y], 1);
        }
        *(int2*)(g_rank + e2 * 2) = make_int2(r0, r1);
    } else if (e2 * 2 < Ee) {
        int c = cols[e2 * 2];
        if ((unsigned)c < Nn) {
            atomicAdd(&g_deg[c], ew[e2 * 2]);
            g_rank[e2 * 2] = atomicAdd(&g_cnt[c], 1);
        }
    }
}

// ---------------------------------------------------------------------------
// 3-phase exclusive scan of g_cnt -> g_off (+ dinv fused in phase 3)
// ---------------------------------------------------------------------------
__global__ void __launch_bounds__(1024)
scan_sum_kernel() {
    __shared__ int sm[1024];
    int t = threadIdx.x;
    int i = blockIdx.x * 1024 + t;
    sm[t] = (i < Nn) ? g_cnt[i] : 0;
    __syncthreads();
    for (int d = 512; d > 0; d >>= 1) {
        if (t < d) sm[t] += sm[t + d];
        __syncthreads();
    }
    if (t == 0) g_bsum[blockIdx.x] = sm[0];
}

__global__ void __launch_bounds__(128)
scan_base_kernel() {
    __shared__ int sm[128];
    int t = threadIdx.x;
    int v = (t < SCAN_B) ? g_bsum[t] : 0;
    sm[t] = v;
    __syncthreads();
    for (int d = 1; d < 128; d <<= 1) {
        int u = (t >= d) ? sm[t - d] : 0;
        __syncthreads();
        sm[t] += u;
        __syncthreads();
    }
    if (t < SCAN_B) g_bbase[t] = sm[t] - v;  // exclusive
}

__global__ void __launch_bounds__(1024)
scan_final_kernel() {
    __shared__ int sm[1024];
    int t = threadIdx.x;
    int i = blockIdx.x * 1024 + t;
    int v = (i < Nn) ? g_cnt[i] : 0;
    sm[t] = v;
    __syncthreads();
    for (int d = 1; d < 1024; d <<= 1) {
        int u = (t >= d) ? sm[t - d] : 0;
        __syncthreads();
        sm[t] += u;
        __syncthreads();
    }
    if (i < Nn) {
        g_off[i] = g_bbase[blockIdx.x] + sm[t] - v;
        float d = g_deg[i];                      // dinv fused here
        g_dinv[i] = d > 0.f ? rsqrtf(d) : 0.f;
    }
}

// ---------------------------------------------------------------------------
// Scatter edges into packed CSR slots — NO atomics (rank precomputed).
// ---------------------------------------------------------------------------
__global__ void scatter_kernel(const int* __restrict__ rows,
                               const int* __restrict__ cols,
                               const float* __restrict__ ew) {
    int e2 = blockIdx.x * blockDim.x + threadIdx.x;
    if (e2 * 2 + 1 < Ee) {
        int2 r = *(const int2*)(rows + e2 * 2);
        int2 c = *(const int2*)(cols + e2 * 2);
        float2 w = *(const float2*)(ew + e2 * 2);
        int2 rk = *(const int2*)(g_rank + e2 * 2);
        if ((unsigned)r.x < Nn && (unsigned)c.x < Nn) {
            int p = g_off[c.x] + rk.x;
            g_csr[p] = make_int2(r.x, __float_as_int(g_dinv[r.x] * w.x * g_dinv[c.x]));
        }
        if ((unsigned)r.y < Nn && (unsigned)c.y < Nn) {
            int p = g_off[c.y] + rk.y;
            g_csr[p] = make_int2(r.y, __float_as_int(g_dinv[r.y] * w.y * g_dinv[c.y]));
        }
    } else if (e2 * 2 < Ee) {
        int r = rows[e2 * 2], c = cols[e2 * 2];
        if ((unsigned)r < Nn && (unsigned)c < Nn) {
            int p = g_off[c] + g_rank[e2 * 2];
            g_csr[p] = make_int2(r, __float_as_int(g_dinv[r] * ew[e2 * 2] * g_dinv[c]));
        }
    }
}

// ---------------------------------------------------------------------------
// SpMM gather (fp16 src, fp16 dst): agg16[n] = sum nw * h16[row].
// One warp per node, lane owns 2 feats. 4 independent streams for MLP.
// ---------------------------------------------------------------------------
__global__ void __launch_bounds__(256)
gather_kernel(int src) {
    int w = (blockIdx.x * 256 + threadIdx.x) >> 5;   // node id
    int lane = threadIdx.x & 31;
    if (w >= Nn) return;
    const __half* __restrict__ h = src ? g_o16 : g_h16;
    int beg = g_off[w];
    int end = beg + g_cnt[w];
    float2 a0 = make_float2(0.f, 0.f);
    float2 a1 = make_float2(0.f, 0.f);
    float2 a2 = make_float2(0.f, 0.f);
    float2 a3 = make_float2(0.f, 0.f);
    int j = beg;
    for (; j + 4 <= end; j += 4) {
        int2 c0 = g_csr[j];
        int2 c1 = g_csr[j + 1];
        int2 c2 = g_csr[j + 2];
        int2 c3 = g_csr[j + 3];
        float2 v0 = __half22float2(*(const __half2*)(h + (size_t)c0.x * Ff + lane * 2));
        float2 v1 = __half22float2(*(const __half2*)(h + (size_t)c1.x * Ff + lane * 2));
        float2 v2 = __half22float2(*(const __half2*)(h + (size_t)c2.x * Ff + lane * 2));
        float2 v3 = __half22float2(*(const __half2*)(h + (size_t)c3.x * Ff + lane * 2));
        float w0 = __int_as_float(c0.y), w1 = __int_as_float(c1.y);
        float w2 = __int_as_float(c2.y), w3 = __int_as_float(c3.y);
        a0.x = fmaf(w0, v0.x, a0.x); a0.y = fmaf(w0, v0.y, a0.y);
        a1.x = fmaf(w1, v1.x, a1.x); a1.y = fmaf(w1, v1.y, a1.y);
        a2.x = fmaf(w2, v2.x, a2.x); a2.y = fmaf(w2, v2.y, a2.y);
        a3.x = fmaf(w3, v3.x, a3.x); a3.y = fmaf(w3, v3.y, a3.y);
    }
    for (; j < end; j++) {
        int2 c0 = g_csr[j];
        float2 v0 = __half22float2(*(const __half2*)(h + (size_t)c0.x * Ff + lane * 2));
        float w0 = __int_as_float(c0.y);
        a0.x = fmaf(w0, v0.x, a0.x); a0.y = fmaf(w0, v0.y, a0.y);
    }
    a0.x += a1.x + a2.x + a3.x;
    a0.y += a1.y + a2.y + a3.y;
    *(__half2*)(g_agg16 + (size_t)w * Ff + lane * 2) = __floats2half2_rn(a0.x, a0.y);
}

// ---------------------------------------------------------------------------
// GEMM h0 = relu(x @ W0^T + b).  FFMA (fully hidden under the CSR chain).
// Also writes fp16 shadow for the gather.
// ---------------------------------------------------------------------------
__global__ void __launch_bounds__(256)
gemm_h0_kernel(const float* __restrict__ x, const float* __restrict__ w0,
               const float* __restrict__ b) {
    __shared__ __align__(16) float As[64][128];  // [k][node]
    __shared__ __align__(16) float Ws[64][64];   // [k][f]
    int t = threadIdx.x;
    int n0 = blockIdx.x * 128;

    for (int i = t; i < 4096; i += 256) {
        int k = i >> 6, f = i & 63;
        Ws[k][f] = w0[f * 64 + k];  // transpose: need W0[f][k] at [k][f]
    }
    for (int i = t * 4; i < 8192; i += 1024) {
        int node = i >> 6, k = i & 63;
        int gn = n0 + node;
        float4 v = make_float4(0.f, 0.f, 0.f, 0.f);
        if (gn < Nn) v = *(const float4*)(x + (size_t)gn * 64 + k);
        As[k + 0][node] = v.x; As[k + 1][node] = v.y;
        As[k + 2][node] = v.z; As[k + 3][node] = v.w;
    }
    __syncthreads();

    int tf = (t & 15) * 4;
    int tn = (t >> 4) * 8;
    float acc[8][4];
#pragma unroll
    for (int j = 0; j < 8; j++)
        acc[j][0] = acc[j][1] = acc[j][2] = acc[j][3] = 0.f;

#pragma unroll 8
    for (int k = 0; k < 64; k++) {
        float4 w4 = *(const float4*)&Ws[k][tf];
        float4 b0v = *(const float4*)&As[k][tn];
        float4 b1v = *(const float4*)&As[k][tn + 4];
        float a[8] = {b0v.x, b0v.y, b0v.z, b0v.w, b1v.x, b1v.y, b1v.z, b1v.w};
#pragma unroll
        for (int j = 0; j < 8; j++) {
            acc[j][0] = fmaf(a[j], w4.x, acc[j][0]);
            acc[j][1] = fmaf(a[j], w4.y, acc[j][1]);
            acc[j][2] = fmaf(a[j], w4.z, acc[j][2]);
            acc[j][3] = fmaf(a[j], w4.w, acc[j][3]);
        }
    }
    float4 bv = *(const float4*)(b + tf);
#pragma unroll
    for (int j = 0; j < 8; j++) {
        int gn = n0 + tn + j;
        if (gn < Nn) {
            float4 r;
            r.x = fmaxf(acc[j][0] + bv.x, 0.f);
            r.y = fmaxf(acc[j][1] + bv.y, 0.f);
            r.z = fmaxf(acc[j][2] + bv.z, 0.f);
            r.w = fmaxf(acc[j][3] + bv.w, 0.f);
            *(float4*)&g_h0[(size_t)gn * 64 + tf] = r;
            __half2 p0 = __floats2half2_rn(r.x, r.y);
            __half2 p1 = __floats2half2_rn(r.z, r.w);
            *(__half2*)&g_h16[(size_t)gn * 64 + tf] = p0;
            *(__half2*)&g_h16[(size_t)gn * 64 + tf + 2] = p1;
        }
    }
}

// ---------------------------------------------------------------------------
// Fused conv GEMM (packed f32x2 FFMA2 main loop):
//   out = prev + relu( (0.1*agg16 + 0.9*h0) @ W1 )
// layer 0: prev = h0,   out = g_out1 (+ fp16 shadow g_o16)
// layer 1: prev = out1, out = d_out
// ---------------------------------------------------------------------------
__global__ void __launch_bounds__(256)
gemm_conv_kernel(const float* __restrict__ w1, int layer,
                 float* __restrict__ dout) {
    __shared__ __align__(16) float As[64][128];
    __shared__ __align__(16) float Ws[64][64];
    int t = threadIdx.x;
    int n0 = blockIdx.x * 128;
    const float* __restrict__ prev = layer ? g_out1 : g_h0;
    float* __restrict__ out = layer ? dout : g_out1;

    for (int i = t; i < 4096; i += 256) {
        Ws[i >> 6][i & 63] = w1[i];  // already [k][f]
    }
    for (int i = t * 4; i < 8192; i += 1024) {
        int node = i >> 6, k = i & 63;
        int gn = n0 + node;
        float4 v = make_float4(0.f, 0.f, 0.f, 0.f);
        if (gn < Nn) {
            float2 alo = __half22float2(*(const __half2*)(g_agg16 + (size_t)gn * 64 + k));
            float2 ahi = __half22float2(*(const __half2*)(g_agg16 + (size_t)gn * 64 + k + 2));
            float4 h = *(const float4*)(g_h0 + (size_t)gn * 64 + k);
            v.x = fmaf(0.1f, alo.x, 0.9f * h.x);
            v.y = fmaf(0.1f, alo.y, 0.9f * h.y);
            v.z = fmaf(0.1f, ahi.x, 0.9f * h.z);
            v.w = fmaf(0.1f, ahi.y, 0.9f * h.w);
        }
        As[k + 0][node] = v.x; As[k + 1][node] = v.y;
        As[k + 2][node] = v.z; As[k + 3][node] = v.w;
    }
    __syncthreads();

    int tf = (t & 15) * 4;
    int tn = (t >> 4) * 8;

    // Packed accumulators: acc2[jp][c] holds (acc[2jp][c], acc[2jp+1][c]).
    ull acc2[4][4];
#pragma unroll
    for (int jp = 0; jp < 4; jp++)
#pragma unroll
        for (int c = 0; c < 4; c++) acc2[jp][c] = 0ull;

#pragma unroll 8
    for (int k = 0; k < 64; k++) {
        float4 w4 = *(const float4*)&Ws[k][tf];
        ull wd0 = dup2(w4.x), wd1 = dup2(w4.y), wd2 = dup2(w4.z), wd3 = dup2(w4.w);
        ulonglong2 ap0 = *(const ulonglong2*)&As[k][tn];      // (a0,a1) (a2,a3)
        ulonglong2 ap1 = *(const ulonglong2*)&As[k][tn + 4];  // (a4,a5) (a6,a7)
        ull ap[4] = {ap0.x, ap0.y, ap1.x, ap1.y};
#pragma unroll
        for (int jp = 0; jp < 4; jp++) {
            acc2[jp][0] = fma2(ap[jp], wd0, acc2[jp][0]);
            acc2[jp][1] = fma2(ap[jp], wd1, acc2[jp][1]);
            acc2[jp][2] = fma2(ap[jp], wd2, acc2[jp][2]);
            acc2[jp][3] = fma2(ap[jp], wd3, acc2[jp][3]);
        }
    }

    float acc[8][4];
#pragma unroll
    for (int jp = 0; jp < 4; jp++)
#pragma unroll
        for (int c = 0; c < 4; c++)
            unpack2(acc2[jp][c], acc[2 * jp][c], acc[2 * jp + 1][c]);

#pragma unroll
    for (int j = 0; j < 8; j++) {
        int gn = n0 + tn + j;
        if (gn < Nn) {
            float4 p = *(const float4*)(prev + (size_t)gn * 64 + tf);
            float4 r;
            r.x = p.x + fmaxf(acc[j][0], 0.f);
            r.y = p.y + fmaxf(acc[j][1], 0.f);
            r.z = p.z + fmaxf(acc[j][2], 0.f);
            r.w = p.w + fmaxf(acc[j][3], 0.f);
            *(float4*)(out + (size_t)gn * 64 + tf) = r;
            if (layer == 0) {
                __half2 p0 = __floats2half2_rn(r.x, r.y);
                __half2 p1 = __floats2half2_rn(r.z, r.w);
                *(__half2*)&g_o16[(size_t)gn * 64 + tf] = p0;
                *(__half2*)&g_o16[(size_t)gn * 64 + tf + 2] = p1;
            }
        }
    }
}

// ---------------------------------------------------------------------------
extern "C" void kernel_launch(void* const* d_in, const int* in_sizes, int n_in,
                              void* d_out, int out_size) {
    const float* x  = (const float*)d_in[0];
    const int*   ei = (const int*)d_in[1];   // int32 (harness: int64 -> int32)
    const float* ew = (const float*)d_in[2];
    // d_in[3] = edge_attr (unused by the module)
    const float* w0 = (const float*)d_in[4];
    const float* b0 = (const float*)d_in[5];
    const float* w1 = (const float*)d_in[6];
    float* out = (float*)d_out;

    const int* rows = ei;
    const int* cols = ei + Ee;

    const int E2B = (Ee / 2 + 255) / 256;   // 2 edges per thread
    const int NB = (Nn + 255) / 256;
    const int GB = (Nn + 127) / 128;
    const int WB = (Nn + 7) / 8;

    static cudaStream_t s1 = nullptr;
    static cudaEvent_t ev_fork = nullptr, ev_join = nullptr;
    if (s1 == nullptr) {
        cudaStreamCreateWithFlags(&s1, cudaStreamNonBlocking);
        cudaEventCreateWithFlags(&ev_fork, cudaEventDisableTiming);
        cudaEventCreateWithFlags(&ev_join, cudaEventDisableTiming);
    }

    // Fork: gemm_h0 is independent of the CSR build chain.
    cudaEventRecord(ev_fork, 0);
    cudaStreamWaitEvent(s1, ev_fork, 0);
    gemm_h0_kernel<<<GB, 256, 0, s1>>>(x, w0, b0);
    cudaEventRecord(ev_join, s1);

    // CSR build chain on the main stream.
    zero_kernel<<<NB, 256>>>();
    deg_kernel<<<E2B, 256>>>(cols, ew);
    scan_sum_kernel<<<SCAN_B, 1024>>>();
    scan_base_kernel<<<1, 128>>>();
    scan_final_kernel<<<SCAN_B, 1024>>>();   // also computes dinv
    scatter_kernel<<<E2B, 256>>>(rows, cols, ew);

    // Join: gather needs both h0 and the CSR.
    cudaStreamWaitEvent(0, ev_join, 0);

    // layer 1
    gather_kernel<<<WB, 256>>>(0);
    gemm_conv_kernel<<<GB, 256>>>(w1, 0, out);

    // layer 2
    gather_kernel<<<WB, 256>>>(1);
    gemm_conv_kernel<<<GB, 256>>>(w1 + 64 * 64, 1, out);
}